// round 1
// baseline (speedup 1.0000x reference)
#include <cuda_runtime.h>
#include <cuda_bf16.h>

// Problem constants
#define BATCH 8
#define SEQ   2048
#define CDIM  1024
#define NHEAD 16
#define HDIM  64
#define N3C   3072
#define BH    (BATCH * NHEAD)          // 128

// Scratch: q/k/v in (B, H, T, d) layout, fp32. 64 MB each (bss, no allocation).
__device__ float g_q[BATCH * NHEAD * SEQ * HDIM];
__device__ float g_k[BATCH * NHEAD * SEQ * HDIM];
__device__ float g_v[BATCH * NHEAD * SEQ * HDIM];
__device__ int   g_cnt[BATCH];
__device__ int   g_kidx[BATCH * SEQ];

// ---------------------------------------------------------------------------
// Kernel 0: per-batch stable compaction of unmasked key indices.
// mask shape (B,1,1,T) int32, values in {0,1}. 8 blocks x 64 threads.
// ---------------------------------------------------------------------------
__global__ void scan_mask(const int* __restrict__ mask) {
    int b = blockIdx.x;
    int t = threadIdx.x;                 // 64 threads, each owns a 32-chunk
    __shared__ int partial[64];
    __shared__ int offs[64];
    const int* mb = mask + b * SEQ;

    int cnt = 0;
    #pragma unroll
    for (int i = 0; i < 32; i++) cnt += (mb[t * 32 + i] != 0);
    partial[t] = cnt;
    __syncthreads();
    if (t == 0) {
        int s = 0;
        for (int i = 0; i < 64; i++) { offs[i] = s; s += partial[i]; }
        g_cnt[b] = s;
    }
    __syncthreads();
    int o = offs[t];
    for (int i = 0; i < 32; i++) {
        int idx = t * 32 + i;
        if (mb[idx] != 0) g_kidx[b * SEQ + (o++)] = idx;
    }
}

// ---------------------------------------------------------------------------
// Kernel 1: QKV projection GEMM (fp32 SIMT).
// X (16384 x 1024) row-major, W (1024 x 3072) row-major.
// Block tile 128x128, K-step 16, 256 threads, 8x8 per thread.
// Epilogue: + bias, q pre-scaled by d^-0.5, scatter to (B,H,T,d).
// ---------------------------------------------------------------------------
#define GM 128
#define GN 128
#define GK 16

__global__ __launch_bounds__(256) void qkv_gemm(const float* __restrict__ X,
                                                const float* __restrict__ W,
                                                const float* __restrict__ bias) {
    __shared__ float As[GK][GM + 4];   // transposed A, stride 132 (16B-aligned rows)
    __shared__ float Bs[GK][GN];

    int tid = threadIdx.x;
    int tx = tid & 15;                 // 16 cols of threads
    int ty = tid >> 4;                 // 16 rows of threads
    int n0 = blockIdx.x * GN;
    int m0 = blockIdx.y * GM;

    const float* Ablk = X + (size_t)m0 * CDIM;

    float acc[8][8];
    #pragma unroll
    for (int i = 0; i < 8; i++)
        #pragma unroll
        for (int j = 0; j < 8; j++) acc[i][j] = 0.0f;

    for (int kt = 0; kt < CDIM; kt += GK) {
        // Load A tile: 128 rows x 16 cols = 512 float4 (2 per thread), transposed.
        #pragma unroll
        for (int it = 0; it < 2; it++) {
            int idx = it * 256 + tid;          // 0..511
            int ar = idx >> 2;                 // row 0..127
            int ac = (idx & 3) * 4;            // col 0,4,8,12
            float4 v = *(const float4*)(Ablk + ar * CDIM + kt + ac);
            As[ac + 0][ar] = v.x;
            As[ac + 1][ar] = v.y;
            As[ac + 2][ar] = v.z;
            As[ac + 3][ar] = v.w;
        }
        // Load B tile: 16 rows x 128 cols = 512 float4 (2 per thread).
        #pragma unroll
        for (int it = 0; it < 2; it++) {
            int idx = it * 256 + tid;
            int br = idx >> 5;                 // 0..15
            int bc = (idx & 31) * 4;           // 0..124
            *(float4*)&Bs[br][bc] = *(const float4*)(W + (size_t)(kt + br) * N3C + n0 + bc);
        }
        __syncthreads();

        #pragma unroll
        for (int k = 0; k < GK; k++) {
            float a[8], bb[8];
            *(float4*)&a[0] = *(const float4*)&As[k][ty * 8];
            *(float4*)&a[4] = *(const float4*)&As[k][ty * 8 + 4];
            *(float4*)&bb[0] = *(const float4*)&Bs[k][tx * 8];
            *(float4*)&bb[4] = *(const float4*)&Bs[k][tx * 8 + 4];
            #pragma unroll
            for (int i = 0; i < 8; i++)
                #pragma unroll
                for (int j = 0; j < 8; j++)
                    acc[i][j] += a[i] * bb[j];
        }
        __syncthreads();
    }

    // Epilogue: bias + scatter. Thread's 8 cols are consecutive (tx*8..+7),
    // all within the same sel (q/k/v) and same head (dd stays inside 64-block).
    int colbase = n0 + tx * 8;
    int sel = colbase >> 10;               // 0=q 1=k 2=v
    int cc  = colbase & 1023;
    int h   = cc >> 6;
    int dd0 = cc & 63;
    float* dst = (sel == 0) ? g_q : (sel == 1) ? g_k : g_v;
    float scale = (sel == 0) ? 0.125f : 1.0f;   // d^-0.5 fused into q

    float bvals[8];
    #pragma unroll
    for (int j = 0; j < 8; j++) bvals[j] = bias[colbase + j];

    #pragma unroll
    for (int i = 0; i < 8; i++) {
        int row = m0 + ty * 8 + i;         // global token index
        int bb_ = row >> 11;               // /SEQ
        int tt  = row & (SEQ - 1);
        size_t base = ((size_t)((bb_ * NHEAD + h) * SEQ) + tt) * HDIM + dd0;
        float4 o0, o1;
        o0.x = (acc[i][0] + bvals[0]) * scale;
        o0.y = (acc[i][1] + bvals[1]) * scale;
        o0.z = (acc[i][2] + bvals[2]) * scale;
        o0.w = (acc[i][3] + bvals[3]) * scale;
        o1.x = (acc[i][4] + bvals[4]) * scale;
        o1.y = (acc[i][5] + bvals[5]) * scale;
        o1.z = (acc[i][6] + bvals[6]) * scale;
        o1.w = (acc[i][7] + bvals[7]) * scale;
        *(float4*)&dst[base]     = o0;
        *(float4*)&dst[base + 4] = o1;
    }
}

// ---------------------------------------------------------------------------
// Kernel 2: flash attention over compacted keys (fp32 SIMT).
// Grid: (32 q-tiles, 128 bh). Block: 256 threads, Br=Bc=64, 4x4 per thread.
// Output written directly into the (B,H,T,d)-contiguous out buffer
// (the reference's reshape without transpose makes these byte-identical).
// ---------------------------------------------------------------------------
__global__ __launch_bounds__(256) void flash_attn(float* __restrict__ out) {
    __shared__ float Qs[HDIM][68];     // [dd][row], pad 68 -> 16B-aligned rows
    __shared__ float Ks[HDIM][68];     // [dd][key]
    __shared__ float Vs[64][HDIM];     // [key][dd]
    __shared__ float Ps[64][68];       // [row][key]

    int tid = threadIdx.x;
    int tx = tid & 15;                 // key / out-dim columns (4 each)
    int ty = tid >> 4;                 // query rows (4 each)
    int bh = blockIdx.y;               // 0..127
    int b  = bh >> 4;
    int q0 = blockIdx.x * 64;

    int cnt = g_cnt[b];
    const int* kidx = g_kidx + b * SEQ;
    const float* Qg = g_q + ((size_t)bh * SEQ + q0) * HDIM;
    const float* Kg = g_k + (size_t)bh * SEQ * HDIM;
    const float* Vg = g_v + (size_t)bh * SEQ * HDIM;

    // Load Q tile transposed: Qs[dd][row]
    #pragma unroll
    for (int it = 0; it < 4; it++) {
        int idx = it * 256 + tid;      // float4 units, 0..1023
        int r  = idx >> 4;             // row 0..63
        int c4 = (idx & 15) * 4;       // dd
        float4 v = *(const float4*)(Qg + r * HDIM + c4);
        Qs[c4 + 0][r] = v.x;
        Qs[c4 + 1][r] = v.y;
        Qs[c4 + 2][r] = v.z;
        Qs[c4 + 3][r] = v.w;
    }

    float m[4], lp[4], accv[4][4];
    #pragma unroll
    for (int r = 0; r < 4; r++) {
        m[r] = -1e30f;
        lp[r] = 0.0f;
        #pragma unroll
        for (int c = 0; c < 4; c++) accv[r][c] = 0.0f;
    }

    int ntiles = (cnt + 63) >> 6;
    for (int t = 0; t < ntiles; t++) {
        int kbase = t * 64;
        __syncthreads();   // previous PV reads of Vs / first-time Q writes done

        // Gather K (transposed) and V tiles through the compaction index.
        #pragma unroll
        for (int it = 0; it < 4; it++) {
            int idx = it * 256 + tid;
            int j  = idx >> 4;             // tile-local key 0..63
            int c4 = (idx & 15) * 4;
            int kj = kbase + j;
            float4 kv, vv;
            if (kj < cnt) {
                int src = kidx[kj];
                kv = *(const float4*)(Kg + src * HDIM + c4);
                vv = *(const float4*)(Vg + src * HDIM + c4);
            } else {
                kv = make_float4(0.f, 0.f, 0.f, 0.f);
                vv = make_float4(0.f, 0.f, 0.f, 0.f);
            }
            Ks[c4 + 0][j] = kv.x;
            Ks[c4 + 1][j] = kv.y;
            Ks[c4 + 2][j] = kv.z;
            Ks[c4 + 3][j] = kv.w;
            *(float4*)&Vs[j][c4] = vv;
        }
        __syncthreads();

        // S = Q K^T  (q already carries the d^-0.5 scale)
        float s[4][4];
        #pragma unroll
        for (int r = 0; r < 4; r++)
            #pragma unroll
            for (int c = 0; c < 4; c++) s[r][c] = 0.0f;

        #pragma unroll 8
        for (int kk = 0; kk < HDIM; kk++) {
            float qv[4], kv[4];
            *(float4*)qv = *(const float4*)&Qs[kk][ty * 4];
            *(float4*)kv = *(const float4*)&Ks[kk][tx * 4];
            #pragma unroll
            for (int r = 0; r < 4; r++)
                #pragma unroll
                for (int c = 0; c < 4; c++)
                    s[r][c] += qv[r] * kv[c];
        }

        // Mask padded tail keys
        #pragma unroll
        for (int c = 0; c < 4; c++) {
            if (kbase + tx * 4 + c >= cnt) {
                s[0][c] = -1e30f; s[1][c] = -1e30f;
                s[2][c] = -1e30f; s[3][c] = -1e30f;
            }
        }

        // Online softmax per row (rows live in 16 tx-lanes of the same half-warp)
        #pragma unroll
        for (int r = 0; r < 4; r++) {
            float mt = fmaxf(fmaxf(s[r][0], s[r][1]), fmaxf(s[r][2], s[r][3]));
            mt = fmaxf(mt, __shfl_xor_sync(0xffffffffu, mt, 1));
            mt = fmaxf(mt, __shfl_xor_sync(0xffffffffu, mt, 2));
            mt = fmaxf(mt, __shfl_xor_sync(0xffffffffu, mt, 4));
            mt = fmaxf(mt, __shfl_xor_sync(0xffffffffu, mt, 8));
            float mn = fmaxf(m[r], mt);
            float sc = __expf(m[r] - mn);
            m[r] = mn;
            float rs = 0.0f;
            #pragma unroll
            for (int c = 0; c < 4; c++) {
                float p = __expf(s[r][c] - mn);
                s[r][c] = p;
                rs += p;
            }
            lp[r] = lp[r] * sc + rs;
            #pragma unroll
            for (int c = 0; c < 4; c++) accv[r][c] *= sc;
            *(float4*)&Ps[ty * 4 + r][tx * 4] =
                make_float4(s[r][0], s[r][1], s[r][2], s[r][3]);
        }
        __syncthreads();

        // O += P V
        #pragma unroll 8
        for (int kc = 0; kc < 64; kc++) {
            float pv[4];
            #pragma unroll
            for (int r = 0; r < 4; r++) pv[r] = Ps[ty * 4 + r][kc];
            float vv[4];
            *(float4*)vv = *(const float4*)&Vs[kc][tx * 4];
            #pragma unroll
            for (int r = 0; r < 4; r++)
                #pragma unroll
                for (int c = 0; c < 4; c++)
                    accv[r][c] += pv[r] * vv[c];
        }
    }

    // Finalize: reduce partial row-sums across tx, normalize, store.
    #pragma unroll
    for (int r = 0; r < 4; r++) {
        float l = lp[r];
        l += __shfl_xor_sync(0xffffffffu, l, 1);
        l += __shfl_xor_sync(0xffffffffu, l, 2);
        l += __shfl_xor_sync(0xffffffffu, l, 4);
        l += __shfl_xor_sync(0xffffffffu, l, 8);
        float inv = 1.0f / l;
        int row = q0 + ty * 4 + r;
        float4 o = make_float4(accv[r][0] * inv, accv[r][1] * inv,
                               accv[r][2] * inv, accv[r][3] * inv);
        *(float4*)&out[((size_t)bh * SEQ + row) * HDIM + tx * 4] = o;
    }
}

// ---------------------------------------------------------------------------
extern "C" void kernel_launch(void* const* d_in, const int* in_sizes, int n_in,
                              void* d_out, int out_size) {
    const float* x    = (const float*)d_in[0];
    const int*   mask = (const int*)d_in[1];
    const float* W    = (const float*)d_in[2];
    const float* bias = (const float*)d_in[3];
    float* out = (float*)d_out;

    scan_mask<<<BATCH, 64>>>(mask);

    dim3 gg(N3C / GN, (BATCH * SEQ) / GM);   // (24, 128)
    qkv_gemm<<<gg, 256>>>(x, W, bias);

    dim3 fg(SEQ / 64, BH);                   // (32, 128)
    flash_attn<<<fg, 256>>>(out);
}

// round 15
// speedup vs baseline: 2.3913x; 2.3913x over previous
#include <cuda_runtime.h>
#include <cuda_bf16.h>
#include <cstdint>

// Problem constants
#define BATCH 8
#define SEQ   2048
#define CDIM  1024
#define NHEAD 16
#define HDIM  64
#define N3C   3072
#define BH    (BATCH * NHEAD)          // 128

__device__ __forceinline__ uint32_t smem_u32(const void* p) {
    uint32_t a;
    asm("{ .reg .u64 t; cvta.to.shared.u64 t, %1; cvt.u32.u64 %0, t; }"
        : "=r"(a) : "l"(p));
    return a;
}

__device__ __forceinline__ void ldsm4(uint32_t* r, uint32_t addr) {
    asm volatile("ldmatrix.sync.aligned.m8n8.x4.shared.b16 {%0,%1,%2,%3}, [%4];"
        : "=r"(r[0]), "=r"(r[1]), "=r"(r[2]), "=r"(r[3]) : "r"(addr));
}

__device__ __forceinline__ void ldsm4t(uint32_t* r, uint32_t addr) {
    asm volatile("ldmatrix.sync.aligned.m8n8.x4.trans.shared.b16 {%0,%1,%2,%3}, [%4];"
        : "=r"(r[0]), "=r"(r[1]), "=r"(r[2]), "=r"(r[3]) : "r"(addr));
}

__device__ __forceinline__ void mma16816(float* c, const uint32_t* a, const uint32_t* b) {
    asm volatile("mma.sync.aligned.m16n8k16.row.col.f32.bf16.bf16.f32 "
        "{%0,%1,%2,%3}, {%4,%5,%6,%7}, {%8,%9}, {%0,%1,%2,%3};"
        : "+f"(c[0]), "+f"(c[1]), "+f"(c[2]), "+f"(c[3])
        : "r"(a[0]), "r"(a[1]), "r"(a[2]), "r"(a[3]), "r"(b[0]), "r"(b[1]));
}

// pack two fp32 -> bf16x2 reg {lo, hi}
__device__ __forceinline__ uint32_t pack_bf16x2(float lo, float hi) {
    uint32_t r;
    asm("cvt.rn.bf16x2.f32 %0, %1, %2;" : "=r"(r) : "f"(hi), "f"(lo));
    return r;
}

// ---------------------------------------------------------------------------
// Scratch (static device memory; no allocation)
// ---------------------------------------------------------------------------
__device__ int g_cnt[BATCH];
__device__ int g_kidx[BATCH * SEQ];

// bf16 split GEMM operands. X: [16384,1024] K-major. W^T: [3072,1024] K-major.
__device__ __nv_bfloat16 g_xhi[BATCH * SEQ * CDIM];
__device__ __nv_bfloat16 g_xlo[BATCH * SEQ * CDIM];
__device__ __nv_bfloat16 g_whi[N3C * CDIM];
__device__ __nv_bfloat16 g_wlo[N3C * CDIM];

// q/k/v bf16 hi/lo planes in (B,H,T,d); q carries the d^-0.5 scale.
__device__ __nv_bfloat16 g_qh[BATCH * NHEAD * SEQ * HDIM];
__device__ __nv_bfloat16 g_ql[BATCH * NHEAD * SEQ * HDIM];
__device__ __nv_bfloat16 g_kh[BATCH * NHEAD * SEQ * HDIM];
__device__ __nv_bfloat16 g_kl[BATCH * NHEAD * SEQ * HDIM];
__device__ __nv_bfloat16 g_vh[BATCH * NHEAD * SEQ * HDIM];
__device__ __nv_bfloat16 g_vl[BATCH * NHEAD * SEQ * HDIM];

struct __align__(8) bf4 { __nv_bfloat16 v[4]; };

// ---------------------------------------------------------------------------
// Kernel 0: per-batch stable compaction of unmasked key indices.
// ---------------------------------------------------------------------------
__global__ void scan_mask(const int* __restrict__ mask) {
    int b = blockIdx.x;
    int t = threadIdx.x;
    __shared__ int partial[64];
    __shared__ int offs[64];
    const int* mb = mask + b * SEQ;

    int cnt = 0;
    #pragma unroll
    for (int i = 0; i < 32; i++) cnt += (mb[t * 32 + i] != 0);
    partial[t] = cnt;
    __syncthreads();
    if (t == 0) {
        int s = 0;
        for (int i = 0; i < 64; i++) { offs[i] = s; s += partial[i]; }
        g_cnt[b] = s;
    }
    __syncthreads();
    int o = offs[t];
    for (int i = 0; i < 32; i++) {
        int idx = t * 32 + i;
        if (mb[idx] != 0) g_kidx[b * SEQ + (o++)] = idx;
    }
}

// ---------------------------------------------------------------------------
// Kernel A: split X into bf16 hi/lo planes.
// ---------------------------------------------------------------------------
__global__ __launch_bounds__(256) void convert_x(const float* __restrict__ X) {
    size_t i = (size_t)blockIdx.x * 256 + threadIdx.x;   // float4 index
    const float4* X4 = (const float4*)X;
    float4 x = X4[i];
    bf4 h, l;
    float fx[4] = {x.x, x.y, x.z, x.w};
    #pragma unroll
    for (int j = 0; j < 4; j++) {
        __nv_bfloat16 hh = __float2bfloat16(fx[j]);
        h.v[j] = hh;
        l.v[j] = __float2bfloat16(fx[j] - __bfloat162float(hh));
    }
    ((bf4*)g_xhi)[i] = h;
    ((bf4*)g_xlo)[i] = l;
}

// ---------------------------------------------------------------------------
// Kernel B: split + transpose W (1024 x 3072) -> W^T hi/lo (3072 x 1024).
// ---------------------------------------------------------------------------
__global__ __launch_bounds__(256) void convert_w(const float* __restrict__ W) {
    __shared__ float tile[32][33];
    int n0 = blockIdx.x * 32;
    int k0 = blockIdx.y * 32;
    int tx = threadIdx.x;          // 32
    int ty = threadIdx.y;          // 8
    #pragma unroll
    for (int yy = ty; yy < 32; yy += 8)
        tile[yy][tx] = W[(size_t)(k0 + yy) * N3C + n0 + tx];
    __syncthreads();
    #pragma unroll
    for (int yy = ty; yy < 32; yy += 8) {
        float v = tile[tx][yy];    // W[k0+tx][n0+yy]
        __nv_bfloat16 hh = __float2bfloat16(v);
        size_t o = (size_t)(n0 + yy) * CDIM + k0 + tx;
        g_whi[o] = hh;
        g_wlo[o] = __float2bfloat16(v - __bfloat162float(hh));
    }
}

// ---------------------------------------------------------------------------
// Kernel 1: QKV projection on warp-level bf16 HMMA (3-term split).
// CTA 128x128, 8 warps (4x2), warp tile 32x64, K-chunk 32, double-buffered.
// Epilogue writes bf16 hi/lo planes (q scaled by d^-0.5).
// ---------------------------------------------------------------------------
#define KC 32                        // bf16 elements per K-chunk
#define LDT 80                       // smem row stride (bytes)
#define TILE_B (128 * LDT)           // 10240 B per operand tile
#define BUF_B  (4 * TILE_B)          // Ahi, Alo, Bhi, Blo
#define SMEM_GEMM (2 * BUF_B)        // 81920

__device__ __forceinline__ void ldg_chunk(uint4* st, int m0, int n0, int kc, int tid) {
    #pragma unroll
    for (int i = 0; i < 8; i++) {
        int arr = i >> 1;
        int rem = ((i & 1) << 8) | tid;
        int row = rem >> 2;
        int c16 = rem & 3;
        const __nv_bfloat16* src =
            (arr == 0) ? g_xhi + (size_t)(m0 + row) * CDIM :
            (arr == 1) ? g_xlo + (size_t)(m0 + row) * CDIM :
            (arr == 2) ? g_whi + (size_t)(n0 + row) * CDIM :
                         g_wlo + (size_t)(n0 + row) * CDIM;
        st[i] = *(const uint4*)(src + kc + c16 * 8);
    }
}

__device__ __forceinline__ void sts_chunk(char* bufb, const uint4* st, int tid) {
    #pragma unroll
    for (int i = 0; i < 8; i++) {
        int arr = i >> 1;
        int rem = ((i & 1) << 8) | tid;
        int row = rem >> 2;
        int c16 = rem & 3;
        *(uint4*)(bufb + arr * TILE_B + row * LDT + c16 * 16) = st[i];
    }
}

__global__ __launch_bounds__(256) void qkv_gemm_tc(const float* __restrict__ bias) {
    extern __shared__ char smem[];
    uint32_t sb = smem_u32(smem);
    int tid = threadIdx.x;
    int wid = tid >> 5;
    int lane = tid & 31;
    int m0 = blockIdx.y * 128;
    int n0 = blockIdx.x * 128;

    int wm = wid >> 1;               // 0..3 (M)
    int wn = wid & 1;                // 0..1 (N)

    int a_row = lane & 15;
    int a_kb  = (lane >> 4) * 16;
    int b_row = (lane & 7) + ((lane >> 4) & 1) * 8;
    int b_kb  = ((lane >> 3) & 1) * 16;

    float acc[2][8][4];
    #pragma unroll
    for (int mt = 0; mt < 2; mt++)
        #pragma unroll
        for (int nt = 0; nt < 8; nt++)
            #pragma unroll
            for (int j = 0; j < 4; j++) acc[mt][nt][j] = 0.0f;

    uint4 st[8];
    ldg_chunk(st, m0, n0, 0, tid);
    sts_chunk(smem, st, tid);
    __syncthreads();

    const int NCH = CDIM / KC;       // 32
    for (int c = 0; c < NCH; c++) {
        if (c < NCH - 1) ldg_chunk(st, m0, n0, (c + 1) * KC, tid);

        uint32_t bufu = (uint32_t)(c & 1) * BUF_B;
        uint32_t Ahi = sb + bufu;
        uint32_t Alo = Ahi + TILE_B;
        uint32_t Bhi = Ahi + 2 * TILE_B;
        uint32_t Blo = Ahi + 3 * TILE_B;

        #pragma unroll
        for (int kk = 0; kk < 2; kk++) {
            int kb = kk * 32;
            uint32_t ah[2][4], al[2][4];
            #pragma unroll
            for (int mt = 0; mt < 2; mt++) {
                uint32_t ro = (uint32_t)(wm * 32 + mt * 16 + a_row) * LDT + kb + a_kb;
                ldsm4(ah[mt], Ahi + ro);
                ldsm4(al[mt], Alo + ro);
            }
            uint32_t bh[8][2], bl[8][2];
            #pragma unroll
            for (int np = 0; np < 4; np++) {
                uint32_t ro = (uint32_t)(wn * 64 + np * 16 + b_row) * LDT + kb + b_kb;
                uint32_t t4[4];
                ldsm4(t4, Bhi + ro);
                bh[2 * np][0] = t4[0]; bh[2 * np][1] = t4[1];
                bh[2 * np + 1][0] = t4[2]; bh[2 * np + 1][1] = t4[3];
                ldsm4(t4, Blo + ro);
                bl[2 * np][0] = t4[0]; bl[2 * np][1] = t4[1];
                bl[2 * np + 1][0] = t4[2]; bl[2 * np + 1][1] = t4[3];
            }
            #pragma unroll
            for (int mt = 0; mt < 2; mt++)
                #pragma unroll
                for (int nt = 0; nt < 8; nt++) {
                    mma16816(acc[mt][nt], ah[mt], bh[nt]);
                    mma16816(acc[mt][nt], al[mt], bh[nt]);
                    mma16816(acc[mt][nt], ah[mt], bl[nt]);
                }
        }
        __syncthreads();
        if (c < NCH - 1) {
            sts_chunk(smem + ((c + 1) & 1) * BUF_B, st, tid);
            __syncthreads();
        }
    }

    // Epilogue: bias + q-scale + bf16 hi/lo split + scatter to (B,H,T,d)
    int g  = lane >> 2;
    int tg = lane & 3;
    int sel = n0 >> 10;                  // 0=q 1=k 2=v (constant per CTA)
    __nv_bfloat16* dh = (sel == 0) ? g_qh : (sel == 1) ? g_kh : g_vh;
    __nv_bfloat16* dl = (sel == 0) ? g_ql : (sel == 1) ? g_kl : g_vl;
    float scale = (sel == 0) ? 0.125f : 1.0f;

    #pragma unroll
    for (int mt = 0; mt < 2; mt++) {
        #pragma unroll
        for (int nt = 0; nt < 8; nt++) {
            int cg = n0 + wn * 64 + nt * 8 + tg * 2;
            int h  = (cg & 1023) >> 6;
            int dd = cg & 63;
            float b0v = bias[cg];
            float b1v = bias[cg + 1];
            int r0 = m0 + wm * 32 + mt * 16 + g;
            #pragma unroll
            for (int rr = 0; rr < 2; rr++) {
                int row = r0 + rr * 8;
                int bb = row >> 11;
                int t  = row & (SEQ - 1);
                size_t o = ((size_t)((bb * NHEAD + h) * SEQ) + t) * HDIM + dd;
                float vx = (acc[mt][nt][rr * 2 + 0] + b0v) * scale;
                float vy = (acc[mt][nt][rr * 2 + 1] + b1v) * scale;
                __nv_bfloat16 hx = __float2bfloat16(vx);
                __nv_bfloat16 hy = __float2bfloat16(vy);
                float rx = vx - __bfloat162float(hx);
                float ry = vy - __bfloat162float(hy);
                __nv_bfloat162 hp; hp.x = hx; hp.y = hy;
                __nv_bfloat162 lp; lp.x = __float2bfloat16(rx); lp.y = __float2bfloat16(ry);
                *(__nv_bfloat162*)&dh[o] = hp;
                *(__nv_bfloat162*)&dl[o] = lp;
            }
        }
    }
}

// ---------------------------------------------------------------------------
// Kernel 2: flash attention on HMMA over compacted keys.
// CTA: 64q x 64k tiles, 128 threads (4 warps x 16 q-rows).
// QK^T and PV both 3-term bf16 split. Q frags register-resident.
// ---------------------------------------------------------------------------
#define LDF 144                      // smem row stride bytes (64 bf16 + pad)
#define TSZ (64 * LDF)               // 9216 B per plane
#define SMEM_FLASH (4 * TSZ)         // Khi, Klo, Vhi, Vlo = 36864

__global__ __launch_bounds__(128) void flash_attn_tc(float* __restrict__ out) {
    extern __shared__ char fs[];
    uint32_t sb = smem_u32(fs);
    int tid  = threadIdx.x;
    int lane = tid & 31;
    int wid  = tid >> 5;             // 0..3
    int g    = lane >> 2;
    int tg   = lane & 3;
    int bh = blockIdx.y;
    int b  = bh >> 4;
    int q0 = blockIdx.x * 64;

    int cnt = g_cnt[b];
    const int* kidx = g_kidx + b * SEQ;
    const __nv_bfloat16* Qh = g_qh + ((size_t)bh * SEQ + q0) * HDIM;
    const __nv_bfloat16* Ql = g_ql + ((size_t)bh * SEQ + q0) * HDIM;
    const __nv_bfloat16* Kh = g_kh + (size_t)bh * SEQ * HDIM;
    const __nv_bfloat16* Kl = g_kl + (size_t)bh * SEQ * HDIM;
    const __nv_bfloat16* Vh = g_vh + (size_t)bh * SEQ * HDIM;
    const __nv_bfloat16* Vl = g_vl + (size_t)bh * SEQ * HDIM;

    // Stage Q hi/lo into planes 0/1, pull A-fragments into registers.
    #pragma unroll
    for (int i = 0; i < 4; i++) {
        int idx = i * 128 + tid;         // 0..511
        int r = idx >> 3, c = idx & 7;
        *(uint4*)(fs + 0 * TSZ + r * LDF + c * 16) = *(const uint4*)(Qh + r * HDIM + c * 8);
        *(uint4*)(fs + 1 * TSZ + r * LDF + c * 16) = *(const uint4*)(Ql + r * HDIM + c * 8);
    }
    __syncthreads();

    int a_row = lane & 15, a_kb = (lane >> 4) * 16;
    uint32_t qh[4][4], ql[4][4];
    #pragma unroll
    for (int j = 0; j < 4; j++) {
        uint32_t ad = sb + (uint32_t)(wid * 16 + a_row) * LDF + j * 32 + a_kb;
        ldsm4(qh[j], ad);
        ldsm4(ql[j], ad + TSZ);
    }

    int b_row = (lane & 7) + ((lane >> 4) & 1) * 8;   // QK B frags (non-trans)
    int b_kb  = ((lane >> 3) & 1) * 16;
    int v_row = (lane & 7) + ((lane >> 3) & 1) * 8;   // PV B frags (trans)
    int v_cb  = ((lane >> 4) & 1) * 16;

    float m0 = -1e30f, m1 = -1e30f, lp0 = 0.0f, lp1 = 0.0f;
    float accv[8][4];
    #pragma unroll
    for (int nt = 0; nt < 8; nt++)
        #pragma unroll
        for (int j = 0; j < 4; j++) accv[nt][j] = 0.0f;

    int ntiles = (cnt + 63) >> 6;
    for (int t = 0; t < ntiles; t++) {
        int kbase = t * 64;
        __syncthreads();   // prior reads (incl. Q frag staging) done

        // Gather K/V hi/lo tiles through compaction index. 2048 uint4 / 128 thr.
        #pragma unroll
        for (int i = 0; i < 16; i++) {
            int idx = i * 128 + tid;
            int pl  = idx >> 9;
            int rem = idx & 511;
            int r = rem >> 3, c = rem & 7;
            int kj = kbase + r;
            uint4 v = make_uint4(0u, 0u, 0u, 0u);
            if (kj < cnt) {
                int src = kidx[kj];
                const __nv_bfloat16* sp = (pl == 0) ? Kh : (pl == 1) ? Kl
                                        : (pl == 2) ? Vh : Vl;
                v = *(const uint4*)(sp + (size_t)src * HDIM + c * 8);
            }
            *(uint4*)(fs + pl * TSZ + r * LDF + c * 16) = v;
        }
        __syncthreads();

        // S = Q K^T (3-term split)
        float s[8][4];
        #pragma unroll
        for (int nt = 0; nt < 8; nt++)
            #pragma unroll
            for (int j = 0; j < 4; j++) s[nt][j] = 0.0f;

        #pragma unroll
        for (int j = 0; j < 4; j++) {
            #pragma unroll
            for (int kg = 0; kg < 4; kg++) {
                uint32_t ad = sb + (uint32_t)(kg * 16 + b_row) * LDF + j * 32 + b_kb;
                uint32_t th[4], tl[4];
                ldsm4(th, ad);             // Khi plane 0
                ldsm4(tl, ad + TSZ);       // Klo plane 1
                uint32_t h0[2] = {th[0], th[1]}, h1[2] = {th[2], th[3]};
                uint32_t l0[2] = {tl[0], tl[1]}, l1[2] = {tl[2], tl[3]};
                mma16816(s[2 * kg],     qh[j], h0);
                mma16816(s[2 * kg],     ql[j], h0);
                mma16816(s[2 * kg],     qh[j], l0);
                mma16816(s[2 * kg + 1], qh[j], h1);
                mma16816(s[2 * kg + 1], ql[j], h1);
                mma16816(s[2 * kg + 1], qh[j], l1);
            }
        }

        // Mask padded tail keys
        if (kbase + 64 > cnt) {
            #pragma unroll
            for (int nt = 0; nt < 8; nt++) {
                int k0 = kbase + nt * 8 + tg * 2;
                if (k0 >= cnt)     { s[nt][0] = -1e30f; s[nt][2] = -1e30f; }
                if (k0 + 1 >= cnt) { s[nt][1] = -1e30f; s[nt][3] = -1e30f; }
            }
        }

        // Online softmax (rows g and g+8; reduce across tg lanes)
        float mt0 = -1e30f, mt1 = -1e30f;
        #pragma unroll
        for (int nt = 0; nt < 8; nt++) {
            mt0 = fmaxf(mt0, fmaxf(s[nt][0], s[nt][1]));
            mt1 = fmaxf(mt1, fmaxf(s[nt][2], s[nt][3]));
        }
        mt0 = fmaxf(mt0, __shfl_xor_sync(0xffffffffu, mt0, 1));
        mt0 = fmaxf(mt0, __shfl_xor_sync(0xffffffffu, mt0, 2));
        mt1 = fmaxf(mt1, __shfl_xor_sync(0xffffffffu, mt1, 1));
        mt1 = fmaxf(mt1, __shfl_xor_sync(0xffffffffu, mt1, 2));
        float mn0 = fmaxf(m0, mt0), mn1 = fmaxf(m1, mt1);
        float sc0 = __expf(m0 - mn0), sc1 = __expf(m1 - mn1);
        m0 = mn0; m1 = mn1;
        float rs0 = 0.0f, rs1 = 0.0f;
        #pragma unroll
        for (int nt = 0; nt < 8; nt++) {
            s[nt][0] = __expf(s[nt][0] - mn0); rs0 += s[nt][0];
            s[nt][1] = __expf(s[nt][1] - mn0); rs0 += s[nt][1];
            s[nt][2] = __expf(s[nt][2] - mn1); rs1 += s[nt][2];
            s[nt][3] = __expf(s[nt][3] - mn1); rs1 += s[nt][3];
        }
        lp0 = lp0 * sc0 + rs0;
        lp1 = lp1 * sc1 + rs1;
        #pragma unroll
        for (int nt = 0; nt < 8; nt++) {
            accv[nt][0] *= sc0; accv[nt][1] *= sc0;
            accv[nt][2] *= sc1; accv[nt][3] *= sc1;
        }

        // O += P V (C->A repack, 3-term split)
        #pragma unroll
        for (int j = 0; j < 4; j++) {
            float p[8] = { s[2*j][0], s[2*j][1], s[2*j][2], s[2*j][3],
                           s[2*j+1][0], s[2*j+1][1], s[2*j+1][2], s[2*j+1][3] };
            float pr[8];
            #pragma unroll
            for (int e = 0; e < 8; e++)
                pr[e] = p[e] - __bfloat162float(__float2bfloat16(p[e]));
            uint32_t pah[4], pal[4];
            pah[0] = pack_bf16x2(p[0], p[1]);   pah[1] = pack_bf16x2(p[2], p[3]);
            pah[2] = pack_bf16x2(p[4], p[5]);   pah[3] = pack_bf16x2(p[6], p[7]);
            pal[0] = pack_bf16x2(pr[0], pr[1]); pal[1] = pack_bf16x2(pr[2], pr[3]);
            pal[2] = pack_bf16x2(pr[4], pr[5]); pal[3] = pack_bf16x2(pr[6], pr[7]);
            #pragma unroll
            for (int nd = 0; nd < 4; nd++) {
                uint32_t ad = sb + 2 * TSZ + (uint32_t)(16 * j + v_row) * LDF
                            + nd * 32 + v_cb;
                uint32_t tv[4], tw[4];
                ldsm4t(tv, ad);            // Vhi plane 2
                ldsm4t(tw, ad + TSZ);      // Vlo plane 3
                uint32_t v0[2] = {tv[0], tv[1]}, v1[2] = {tv[2], tv[3]};
                uint32_t w0[2] = {tw[0], tw[1]}, w1[2] = {tw[2], tw[3]};
                mma16816(accv[2 * nd],     pah, v0);
                mma16816(accv[2 * nd],     pal, v0);
                mma16816(accv[2 * nd],     pah, w0);
                mma16816(accv[2 * nd + 1], pah, v1);
                mma16816(accv[2 * nd + 1], pal, v1);
                mma16816(accv[2 * nd + 1], pah, w1);
            }
        }
        __syncthreads();
    }

    // Finalize: reduce row sums across tg, normalize, store (B,H,T,d) fp32.
    lp0 += __shfl_xor_sync(0xffffffffu, lp0, 1);
    lp0 += __shfl_xor_sync(0xffffffffu, lp0, 2);
    lp1 += __shfl_xor_sync(0xffffffffu, lp1, 1);
    lp1 += __shfl_xor_sync(0xffffffffu, lp1, 2);
    float inv0 = 1.0f / lp0, inv1 = 1.0f / lp1;
    int r0 = q0 + wid * 16 + g;
    int r1 = r0 + 8;
    #pragma unroll
    for (int nt = 0; nt < 8; nt++) {
        int col = nt * 8 + tg * 2;
        float2 o0 = make_float2(accv[nt][0] * inv0, accv[nt][1] * inv0);
        float2 o1 = make_float2(accv[nt][2] * inv1, accv[nt][3] * inv1);
        *(float2*)&out[((size_t)bh * SEQ + r0) * HDIM + col] = o0;
        *(float2*)&out[((size_t)bh * SEQ + r1) * HDIM + col] = o1;
    }
}

// ---------------------------------------------------------------------------
extern "C" void kernel_launch(void* const* d_in, const int* in_sizes, int n_in,
                              void* d_out, int out_size) {
    const float* x    = (const float*)d_in[0];
    const int*   mask = (const int*)d_in[1];
    const float* W    = (const float*)d_in[2];
    const float* bias = (const float*)d_in[3];
    float* out = (float*)d_out;

    cudaFuncSetAttribute(qkv_gemm_tc, cudaFuncAttributeMaxDynamicSharedMemorySize,
                         SMEM_GEMM);

    scan_mask<<<BATCH, 64>>>(mask);
    convert_x<<<(BATCH * SEQ * CDIM) / (4 * 256), 256>>>(x);
    convert_w<<<dim3(N3C / 32, CDIM / 32), dim3(32, 8)>>>(W);

    dim3 gg(N3C / 128, (BATCH * SEQ) / 128);   // (24, 128)
    qkv_gemm_tc<<<gg, 256, SMEM_GEMM>>>(bias);

    dim3 fg(SEQ / 64, BH);                     // (32, 128)
    flash_attn_tc<<<fg, 128, SMEM_FLASH>>>(out);
}

// round 17
// speedup vs baseline: 2.7190x; 1.1370x over previous
#include <cuda_runtime.h>
#include <cuda_bf16.h>
#include <cstdint>

// Problem constants
#define BATCH 8
#define SEQ   2048
#define CDIM  1024
#define NHEAD 16
#define HDIM  64
#define N3C   3072
#define BH    (BATCH * NHEAD)          // 128

__device__ __forceinline__ uint32_t smem_u32(const void* p) {
    uint32_t a;
    asm("{ .reg .u64 t; cvta.to.shared.u64 t, %1; cvt.u32.u64 %0, t; }"
        : "=r"(a) : "l"(p));
    return a;
}

__device__ __forceinline__ void ldsm4(uint32_t* r, uint32_t addr) {
    asm volatile("ldmatrix.sync.aligned.m8n8.x4.shared.b16 {%0,%1,%2,%3}, [%4];"
        : "=r"(r[0]), "=r"(r[1]), "=r"(r[2]), "=r"(r[3]) : "r"(addr));
}

__device__ __forceinline__ void ldsm4t(uint32_t* r, uint32_t addr) {
    asm volatile("ldmatrix.sync.aligned.m8n8.x4.trans.shared.b16 {%0,%1,%2,%3}, [%4];"
        : "=r"(r[0]), "=r"(r[1]), "=r"(r[2]), "=r"(r[3]) : "r"(addr));
}

__device__ __forceinline__ void mma16816(float* c, const uint32_t* a, const uint32_t* b) {
    asm volatile("mma.sync.aligned.m16n8k16.row.col.f32.bf16.bf16.f32 "
        "{%0,%1,%2,%3}, {%4,%5,%6,%7}, {%8,%9}, {%0,%1,%2,%3};"
        : "+f"(c[0]), "+f"(c[1]), "+f"(c[2]), "+f"(c[3])
        : "r"(a[0]), "r"(a[1]), "r"(a[2]), "r"(a[3]), "r"(b[0]), "r"(b[1]));
}

// pack two fp32 -> bf16x2 reg {lo, hi}
__device__ __forceinline__ uint32_t pack_bf16x2(float lo, float hi) {
    uint32_t r;
    asm("cvt.rn.bf16x2.f32 %0, %1, %2;" : "=r"(r) : "f"(hi), "f"(lo));
    return r;
}

#define CP_ASYNC16(dst, src) \
    asm volatile("cp.async.cg.shared.global [%0], [%1], 16;" \
        :: "r"(dst), "l"(src) : "memory")
#define CP_COMMIT() asm volatile("cp.async.commit_group;" ::: "memory")
#define CP_WAIT1()  asm volatile("cp.async.wait_group 1;" ::: "memory")
#define CP_WAIT0()  asm volatile("cp.async.wait_group 0;" ::: "memory")

// ---------------------------------------------------------------------------
// Scratch (static device memory; no allocation)
// ---------------------------------------------------------------------------
__device__ int g_cnt[BATCH];
__device__ int g_kidx[BATCH * SEQ];

// bf16 split GEMM operands. X: [16384,1024] K-major. W^T: [3072,1024] K-major.
__device__ __nv_bfloat16 g_xhi[BATCH * SEQ * CDIM];
__device__ __nv_bfloat16 g_xlo[BATCH * SEQ * CDIM];
__device__ __nv_bfloat16 g_whi[N3C * CDIM];
__device__ __nv_bfloat16 g_wlo[N3C * CDIM];

// q/k/v bf16 hi/lo planes in (B,H,T,d); q carries the d^-0.5 scale.
__device__ __nv_bfloat16 g_qh[BATCH * NHEAD * SEQ * HDIM];
__device__ __nv_bfloat16 g_ql[BATCH * NHEAD * SEQ * HDIM];
__device__ __nv_bfloat16 g_kh[BATCH * NHEAD * SEQ * HDIM];
__device__ __nv_bfloat16 g_kl[BATCH * NHEAD * SEQ * HDIM];
__device__ __nv_bfloat16 g_vh[BATCH * NHEAD * SEQ * HDIM];
__device__ __nv_bfloat16 g_vl[BATCH * NHEAD * SEQ * HDIM];

struct __align__(8) bf4 { __nv_bfloat16 v[4]; };

// ---------------------------------------------------------------------------
// Kernel 0: per-batch stable compaction of unmasked key indices.
// ---------------------------------------------------------------------------
__global__ void scan_mask(const int* __restrict__ mask) {
    int b = blockIdx.x;
    int t = threadIdx.x;
    __shared__ int partial[64];
    __shared__ int offs[64];
    const int* mb = mask + b * SEQ;

    int cnt = 0;
    #pragma unroll
    for (int i = 0; i < 32; i++) cnt += (mb[t * 32 + i] != 0);
    partial[t] = cnt;
    __syncthreads();
    if (t == 0) {
        int s = 0;
        for (int i = 0; i < 64; i++) { offs[i] = s; s += partial[i]; }
        g_cnt[b] = s;
    }
    __syncthreads();
    int o = offs[t];
    for (int i = 0; i < 32; i++) {
        int idx = t * 32 + i;
        if (mb[idx] != 0) g_kidx[b * SEQ + (o++)] = idx;
    }
}

// ---------------------------------------------------------------------------
// Kernel A: split X into bf16 hi/lo planes.
// ---------------------------------------------------------------------------
__global__ __launch_bounds__(256) void convert_x(const float* __restrict__ X) {
    size_t i = (size_t)blockIdx.x * 256 + threadIdx.x;   // float4 index
    const float4* X4 = (const float4*)X;
    float4 x = X4[i];
    bf4 h, l;
    float fx[4] = {x.x, x.y, x.z, x.w};
    #pragma unroll
    for (int j = 0; j < 4; j++) {
        __nv_bfloat16 hh = __float2bfloat16(fx[j]);
        h.v[j] = hh;
        l.v[j] = __float2bfloat16(fx[j] - __bfloat162float(hh));
    }
    ((bf4*)g_xhi)[i] = h;
    ((bf4*)g_xlo)[i] = l;
}

// ---------------------------------------------------------------------------
// Kernel B: split + transpose W (1024 x 3072) -> W^T hi/lo (3072 x 1024).
// ---------------------------------------------------------------------------
__global__ __launch_bounds__(256) void convert_w(const float* __restrict__ W) {
    __shared__ float tile[32][33];
    int n0 = blockIdx.x * 32;
    int k0 = blockIdx.y * 32;
    int tx = threadIdx.x;          // 32
    int ty = threadIdx.y;          // 8
    #pragma unroll
    for (int yy = ty; yy < 32; yy += 8)
        tile[yy][tx] = W[(size_t)(k0 + yy) * N3C + n0 + tx];
    __syncthreads();
    #pragma unroll
    for (int yy = ty; yy < 32; yy += 8) {
        float v = tile[tx][yy];    // W[k0+tx][n0+yy]
        __nv_bfloat16 hh = __float2bfloat16(v);
        size_t o = (size_t)(n0 + yy) * CDIM + k0 + tx;
        g_whi[o] = hh;
        g_wlo[o] = __float2bfloat16(v - __bfloat162float(hh));
    }
}

// ---------------------------------------------------------------------------
// Kernel 1: QKV projection on warp-level bf16 HMMA (3-term split).
// CTA 128x128, 8 warps (4x2), warp tile 32x64, K-chunk 32.
// cp.async 2-stage pipeline (no register staging) -> regs<=128, 2 CTAs/SM.
// Epilogue writes bf16 hi/lo planes (q scaled by d^-0.5).
// ---------------------------------------------------------------------------
#define KC 32                        // bf16 elements per K-chunk
#define LDT 80                       // smem row stride (bytes)
#define TILE_B (128 * LDT)           // 10240 B per operand tile
#define BUF_B  (4 * TILE_B)          // Ahi, Alo, Bhi, Blo
#define SMEM_GEMM (2 * BUF_B)        // 81920

__device__ __forceinline__ void cpasync_chunk(uint32_t bufb, int m0, int n0,
                                              int kc, int tid) {
    #pragma unroll
    for (int i = 0; i < 8; i++) {
        int arr = i >> 1;
        int rem = ((i & 1) << 8) | tid;
        int row = rem >> 2;
        int c16 = rem & 3;
        const __nv_bfloat16* src =
            (arr == 0) ? g_xhi + (size_t)(m0 + row) * CDIM :
            (arr == 1) ? g_xlo + (size_t)(m0 + row) * CDIM :
            (arr == 2) ? g_whi + (size_t)(n0 + row) * CDIM :
                         g_wlo + (size_t)(n0 + row) * CDIM;
        uint32_t dst = bufb + arr * TILE_B + row * LDT + c16 * 16;
        CP_ASYNC16(dst, src + kc + c16 * 8);
    }
}

__global__ __launch_bounds__(256, 2) void qkv_gemm_tc(const float* __restrict__ bias) {
    extern __shared__ char smem[];
    uint32_t sb = smem_u32(smem);
    int tid = threadIdx.x;
    int wid = tid >> 5;
    int lane = tid & 31;
    int m0 = blockIdx.y * 128;
    int n0 = blockIdx.x * 128;

    int wm = wid >> 1;               // 0..3 (M)
    int wn = wid & 1;                // 0..1 (N)

    int a_row = lane & 15;
    int a_kb  = (lane >> 4) * 16;
    int b_row = (lane & 7) + ((lane >> 4) & 1) * 8;
    int b_kb  = ((lane >> 3) & 1) * 16;

    float acc[2][8][4];
    #pragma unroll
    for (int mt = 0; mt < 2; mt++)
        #pragma unroll
        for (int nt = 0; nt < 8; nt++)
            #pragma unroll
            for (int j = 0; j < 4; j++) acc[mt][nt][j] = 0.0f;

    // Prologue: stage chunks 0 and 1 into the two buffers.
    cpasync_chunk(sb, m0, n0, 0, tid);
    CP_COMMIT();
    cpasync_chunk(sb + BUF_B, m0, n0, KC, tid);
    CP_COMMIT();

    const int NCH = CDIM / KC;       // 32
    for (int c = 0; c < NCH; c++) {
        if (c == NCH - 1) { CP_WAIT0(); } else { CP_WAIT1(); }
        __syncthreads();             // chunk c resident in buf c&1

        uint32_t bufu = (uint32_t)(c & 1) * BUF_B;
        uint32_t Ahi = sb + bufu;
        uint32_t Alo = Ahi + TILE_B;
        uint32_t Bhi = Ahi + 2 * TILE_B;
        uint32_t Blo = Ahi + 3 * TILE_B;

        #pragma unroll
        for (int kk = 0; kk < 2; kk++) {
            int kb = kk * 32;
            uint32_t ah[2][4], al[2][4];
            #pragma unroll
            for (int mt = 0; mt < 2; mt++) {
                uint32_t ro = (uint32_t)(wm * 32 + mt * 16 + a_row) * LDT + kb + a_kb;
                ldsm4(ah[mt], Ahi + ro);
                ldsm4(al[mt], Alo + ro);
            }
            uint32_t bh[8][2], bl[8][2];
            #pragma unroll
            for (int np = 0; np < 4; np++) {
                uint32_t ro = (uint32_t)(wn * 64 + np * 16 + b_row) * LDT + kb + b_kb;
                uint32_t t4[4];
                ldsm4(t4, Bhi + ro);
                bh[2 * np][0] = t4[0]; bh[2 * np][1] = t4[1];
                bh[2 * np + 1][0] = t4[2]; bh[2 * np + 1][1] = t4[3];
                ldsm4(t4, Blo + ro);
                bl[2 * np][0] = t4[0]; bl[2 * np][1] = t4[1];
                bl[2 * np + 1][0] = t4[2]; bl[2 * np + 1][1] = t4[3];
            }
            #pragma unroll
            for (int mt = 0; mt < 2; mt++)
                #pragma unroll
                for (int nt = 0; nt < 8; nt++) {
                    mma16816(acc[mt][nt], ah[mt], bh[nt]);
                    mma16816(acc[mt][nt], al[mt], bh[nt]);
                    mma16816(acc[mt][nt], ah[mt], bl[nt]);
                }
        }
        __syncthreads();             // all warps done reading buf c&1
        if (c + 2 < NCH) {
            cpasync_chunk(sb + bufu, m0, n0, (c + 2) * KC, tid);
            CP_COMMIT();
        }
    }

    // Epilogue: bias + q-scale + bf16 hi/lo split + scatter to (B,H,T,d)
    int g  = lane >> 2;
    int tg = lane & 3;
    int sel = n0 >> 10;                  // 0=q 1=k 2=v (constant per CTA)
    __nv_bfloat16* dh = (sel == 0) ? g_qh : (sel == 1) ? g_kh : g_vh;
    __nv_bfloat16* dl = (sel == 0) ? g_ql : (sel == 1) ? g_kl : g_vl;
    float scale = (sel == 0) ? 0.125f : 1.0f;

    #pragma unroll
    for (int mt = 0; mt < 2; mt++) {
        #pragma unroll
        for (int nt = 0; nt < 8; nt++) {
            int cg = n0 + wn * 64 + nt * 8 + tg * 2;
            int h  = (cg & 1023) >> 6;
            int dd = cg & 63;
            float b0v = bias[cg];
            float b1v = bias[cg + 1];
            int r0 = m0 + wm * 32 + mt * 16 + g;
            #pragma unroll
            for (int rr = 0; rr < 2; rr++) {
                int row = r0 + rr * 8;
                int bb = row >> 11;
                int t  = row & (SEQ - 1);
                size_t o = ((size_t)((bb * NHEAD + h) * SEQ) + t) * HDIM + dd;
                float vx = (acc[mt][nt][rr * 2 + 0] + b0v) * scale;
                float vy = (acc[mt][nt][rr * 2 + 1] + b1v) * scale;
                __nv_bfloat16 hx = __float2bfloat16(vx);
                __nv_bfloat16 hy = __float2bfloat16(vy);
                float rx = vx - __bfloat162float(hx);
                float ry = vy - __bfloat162float(hy);
                __nv_bfloat162 hp; hp.x = hx; hp.y = hy;
                __nv_bfloat162 lp; lp.x = __float2bfloat16(rx); lp.y = __float2bfloat16(ry);
                *(__nv_bfloat162*)&dh[o] = hp;
                *(__nv_bfloat162*)&dl[o] = lp;
            }
        }
    }
}

// ---------------------------------------------------------------------------
// Kernel 2: flash attention on HMMA over compacted keys. (unchanged)
// CTA: 64q x 64k tiles, 128 threads (4 warps x 16 q-rows).
// QK^T and PV both 3-term bf16 split. Q frags register-resident.
// ---------------------------------------------------------------------------
#define LDF 144                      // smem row stride bytes (64 bf16 + pad)
#define TSZ (64 * LDF)               // 9216 B per plane
#define SMEM_FLASH (4 * TSZ)         // Khi, Klo, Vhi, Vlo = 36864

__global__ __launch_bounds__(128) void flash_attn_tc(float* __restrict__ out) {
    extern __shared__ char fs[];
    uint32_t sb = smem_u32(fs);
    int tid  = threadIdx.x;
    int lane = tid & 31;
    int wid  = tid >> 5;             // 0..3
    int g    = lane >> 2;
    int tg   = lane & 3;
    int bh = blockIdx.y;
    int b  = bh >> 4;
    int q0 = blockIdx.x * 64;

    int cnt = g_cnt[b];
    const int* kidx = g_kidx + b * SEQ;
    const __nv_bfloat16* Qh = g_qh + ((size_t)bh * SEQ + q0) * HDIM;
    const __nv_bfloat16* Ql = g_ql + ((size_t)bh * SEQ + q0) * HDIM;
    const __nv_bfloat16* Kh = g_kh + (size_t)bh * SEQ * HDIM;
    const __nv_bfloat16* Kl = g_kl + (size_t)bh * SEQ * HDIM;
    const __nv_bfloat16* Vh = g_vh + (size_t)bh * SEQ * HDIM;
    const __nv_bfloat16* Vl = g_vl + (size_t)bh * SEQ * HDIM;

    // Stage Q hi/lo into planes 0/1, pull A-fragments into registers.
    #pragma unroll
    for (int i = 0; i < 4; i++) {
        int idx = i * 128 + tid;         // 0..511
        int r = idx >> 3, c = idx & 7;
        *(uint4*)(fs + 0 * TSZ + r * LDF + c * 16) = *(const uint4*)(Qh + r * HDIM + c * 8);
        *(uint4*)(fs + 1 * TSZ + r * LDF + c * 16) = *(const uint4*)(Ql + r * HDIM + c * 8);
    }
    __syncthreads();

    int a_row = lane & 15, a_kb = (lane >> 4) * 16;
    uint32_t qh[4][4], ql[4][4];
    #pragma unroll
    for (int j = 0; j < 4; j++) {
        uint32_t ad = sb + (uint32_t)(wid * 16 + a_row) * LDF + j * 32 + a_kb;
        ldsm4(qh[j], ad);
        ldsm4(ql[j], ad + TSZ);
    }

    int b_row = (lane & 7) + ((lane >> 4) & 1) * 8;   // QK B frags (non-trans)
    int b_kb  = ((lane >> 3) & 1) * 16;
    int v_row = (lane & 7) + ((lane >> 3) & 1) * 8;   // PV B frags (trans)
    int v_cb  = ((lane >> 4) & 1) * 16;

    float m0 = -1e30f, m1 = -1e30f, lp0 = 0.0f, lp1 = 0.0f;
    float accv[8][4];
    #pragma unroll
    for (int nt = 0; nt < 8; nt++)
        #pragma unroll
        for (int j = 0; j < 4; j++) accv[nt][j] = 0.0f;

    int ntiles = (cnt + 63) >> 6;
    for (int t = 0; t < ntiles; t++) {
        int kbase = t * 64;
        __syncthreads();   // prior reads (incl. Q frag staging) done

        // Gather K/V hi/lo tiles through compaction index. 2048 uint4 / 128 thr.
        #pragma unroll
        for (int i = 0; i < 16; i++) {
            int idx = i * 128 + tid;
            int pl  = idx >> 9;
            int rem = idx & 511;
            int r = rem >> 3, c = rem & 7;
            int kj = kbase + r;
            uint4 v = make_uint4(0u, 0u, 0u, 0u);
            if (kj < cnt) {
                int src = kidx[kj];
                const __nv_bfloat16* sp = (pl == 0) ? Kh : (pl == 1) ? Kl
                                        : (pl == 2) ? Vh : Vl;
                v = *(const uint4*)(sp + (size_t)src * HDIM + c * 8);
            }
            *(uint4*)(fs + pl * TSZ + r * LDF + c * 16) = v;
        }
        __syncthreads();

        // S = Q K^T (3-term split)
        float s[8][4];
        #pragma unroll
        for (int nt = 0; nt < 8; nt++)
            #pragma unroll
            for (int j = 0; j < 4; j++) s[nt][j] = 0.0f;

        #pragma unroll
        for (int j = 0; j < 4; j++) {
            #pragma unroll
            for (int kg = 0; kg < 4; kg++) {
                uint32_t ad = sb + (uint32_t)(kg * 16 + b_row) * LDF + j * 32 + b_kb;
                uint32_t th[4], tl[4];
                ldsm4(th, ad);             // Khi plane 0
                ldsm4(tl, ad + TSZ);       // Klo plane 1
                uint32_t h0[2] = {th[0], th[1]}, h1[2] = {th[2], th[3]};
                uint32_t l0[2] = {tl[0], tl[1]}, l1[2] = {tl[2], tl[3]};
                mma16816(s[2 * kg],     qh[j], h0);
                mma16816(s[2 * kg],     ql[j], h0);
                mma16816(s[2 * kg],     qh[j], l0);
                mma16816(s[2 * kg + 1], qh[j], h1);
                mma16816(s[2 * kg + 1], ql[j], h1);
                mma16816(s[2 * kg + 1], qh[j], l1);
            }
        }

        // Mask padded tail keys
        if (kbase + 64 > cnt) {
            #pragma unroll
            for (int nt = 0; nt < 8; nt++) {
                int k0 = kbase + nt * 8 + tg * 2;
                if (k0 >= cnt)     { s[nt][0] = -1e30f; s[nt][2] = -1e30f; }
                if (k0 + 1 >= cnt) { s[nt][1] = -1e30f; s[nt][3] = -1e30f; }
            }
        }

        // Online softmax (rows g and g+8; reduce across tg lanes)
        float mt0 = -1e30f, mt1 = -1e30f;
        #pragma unroll
        for (int nt = 0; nt < 8; nt++) {
            mt0 = fmaxf(mt0, fmaxf(s[nt][0], s[nt][1]));
            mt1 = fmaxf(mt1, fmaxf(s[nt][2], s[nt][3]));
        }
        mt0 = fmaxf(mt0, __shfl_xor_sync(0xffffffffu, mt0, 1));
        mt0 = fmaxf(mt0, __shfl_xor_sync(0xffffffffu, mt0, 2));
        mt1 = fmaxf(mt1, __shfl_xor_sync(0xffffffffu, mt1, 1));
        mt1 = fmaxf(mt1, __shfl_xor_sync(0xffffffffu, mt1, 2));
        float mn0 = fmaxf(m0, mt0), mn1 = fmaxf(m1, mt1);
        float sc0 = __expf(m0 - mn0), sc1 = __expf(m1 - mn1);
        m0 = mn0; m1 = mn1;
        float rs0 = 0.0f, rs1 = 0.0f;
        #pragma unroll
        for (int nt = 0; nt < 8; nt++) {
            s[nt][0] = __expf(s[nt][0] - mn0); rs0 += s[nt][0];
            s[nt][1] = __expf(s[nt][1] - mn0); rs0 += s[nt][1];
            s[nt][2] = __expf(s[nt][2] - mn1); rs1 += s[nt][2];
            s[nt][3] = __expf(s[nt][3] - mn1); rs1 += s[nt][3];
        }
        lp0 = lp0 * sc0 + rs0;
        lp1 = lp1 * sc1 + rs1;
        #pragma unroll
        for (int nt = 0; nt < 8; nt++) {
            accv[nt][0] *= sc0; accv[nt][1] *= sc0;
            accv[nt][2] *= sc1; accv[nt][3] *= sc1;
        }

        // O += P V (C->A repack, 3-term split)
        #pragma unroll
        for (int j = 0; j < 4; j++) {
            float p[8] = { s[2*j][0], s[2*j][1], s[2*j][2], s[2*j][3],
                           s[2*j+1][0], s[2*j+1][1], s[2*j+1][2], s[2*j+1][3] };
            float pr[8];
            #pragma unroll
            for (int e = 0; e < 8; e++)
                pr[e] = p[e] - __bfloat162float(__float2bfloat16(p[e]));
            uint32_t pah[4], pal[4];
            pah[0] = pack_bf16x2(p[0], p[1]);   pah[1] = pack_bf16x2(p[2], p[3]);
            pah[2] = pack_bf16x2(p[4], p[5]);   pah[3] = pack_bf16x2(p[6], p[7]);
            pal[0] = pack_bf16x2(pr[0], pr[1]); pal[1] = pack_bf16x2(pr[2], pr[3]);
            pal[2] = pack_bf16x2(pr[4], pr[5]); pal[3] = pack_bf16x2(pr[6], pr[7]);
            #pragma unroll
            for (int nd = 0; nd < 4; nd++) {
                uint32_t ad = sb + 2 * TSZ + (uint32_t)(16 * j + v_row) * LDF
                            + nd * 32 + v_cb;
                uint32_t tv[4], tw[4];
                ldsm4t(tv, ad);            // Vhi plane 2
                ldsm4t(tw, ad + TSZ);      // Vlo plane 3
                uint32_t v0[2] = {tv[0], tv[1]}, v1[2] = {tv[2], tv[3]};
                uint32_t w0[2] = {tw[0], tw[1]}, w1[2] = {tw[2], tw[3]};
                mma16816(accv[2 * nd],     pah, v0);
                mma16816(accv[2 * nd],     pal, v0);
                mma16816(accv[2 * nd],     pah, w0);
                mma16816(accv[2 * nd + 1], pah, v1);
                mma16816(accv[2 * nd + 1], pal, v1);
                mma16816(accv[2 * nd + 1], pah, w1);
            }
        }
        __syncthreads();
    }

    // Finalize: reduce row sums across tg, normalize, store (B,H,T,d) fp32.
    lp0 += __shfl_xor_sync(0xffffffffu, lp0, 1);
    lp0 += __shfl_xor_sync(0xffffffffu, lp0, 2);
    lp1 += __shfl_xor_sync(0xffffffffu, lp1, 1);
    lp1 += __shfl_xor_sync(0xffffffffu, lp1, 2);
    float inv0 = 1.0f / lp0, inv1 = 1.0f / lp1;
    int r0 = q0 + wid * 16 + g;
    int r1 = r0 + 8;
    #pragma unroll
    for (int nt = 0; nt < 8; nt++) {
        int col = nt * 8 + tg * 2;
        float2 o0 = make_float2(accv[nt][0] * inv0, accv[nt][1] * inv0);
        float2 o1 = make_float2(accv[nt][2] * inv1, accv[nt][3] * inv1);
        *(float2*)&out[((size_t)bh * SEQ + r0) * HDIM + col] = o0;
        *(float2*)&out[((size_t)bh * SEQ + r1) * HDIM + col] = o1;
    }
}

// ---------------------------------------------------------------------------
extern "C" void kernel_launch(void* const* d_in, const int* in_sizes, int n_in,
                              void* d_out, int out_size) {
    const float* x    = (const float*)d_in[0];
    const int*   mask = (const int*)d_in[1];
    const float* W    = (const float*)d_in[2];
    const float* bias = (const float*)d_in[3];
    float* out = (float*)d_out;

    cudaFuncSetAttribute(qkv_gemm_tc, cudaFuncAttributeMaxDynamicSharedMemorySize,
                         SMEM_GEMM);

    scan_mask<<<BATCH, 64>>>(mask);
    convert_x<<<(BATCH * SEQ * CDIM) / (4 * 256), 256>>>(x);
    convert_w<<<dim3(N3C / 32, CDIM / 32), dim3(32, 8)>>>(W);

    dim3 gg(N3C / 128, (BATCH * SEQ) / 128);   // (24, 128)
    qkv_gemm_tc<<<gg, 256, SMEM_GEMM>>>(bias);

    dim3 fg(SEQ / 64, BH);                     // (32, 128)
    flash_attn_tc<<<fg, 128, SMEM_FLASH>>>(out);
}